// round 1
// baseline (speedup 1.0000x reference)
#include <cuda_runtime.h>
#include <cuda_fp16.h>
#include <mma.h>
#include <cstdint>

using namespace nvcuda;

#define BB 8
#define SS 1365
#define SP 1408
#define DIM 1024
#define NH 16
#define HD 64
#define MTOT (BB*SS)   // 10920

// ---------------- scratch (device globals; no allocations allowed) ----------------
__device__ __half g_xn[(size_t)BB*SS*DIM];            // LN+mod output, fp16
__device__ float  g_wb[BB*2048];                      // adaln per-batch (w|b)
__device__ float  g_qkv[(size_t)BB*SS*3072];          // qkv GEMM output fp32
__device__ __half g_q[(size_t)BB*NH*SP*HD];           // rope'd, scaled 1/8
__device__ __half g_k[(size_t)BB*NH*SP*HD];
__device__ __half g_v[(size_t)BB*NH*SP*HD];
__device__ __half g_o[(size_t)BB*SS*DIM];             // attention out fp16
__device__ __half g_wqkv[(size_t)DIM*3072];
__device__ __half g_wout[(size_t)DIM*DIM];

// ---------------- helpers ----------------
__device__ __forceinline__ int kend_of(int s) {
    if (s < 1)   return 1;
    if (s < 5)   return 5;
    if (s < 21)  return 21;
    if (s < 85)  return 85;
    if (s < 341) return 341;
    return 1365;
}

__device__ __forceinline__ void pos_of(int s, float* p) {
    if (s == 0) { p[0] = 0.f; p[1] = 0.f; p[2] = 0.f; return; }
    int start, side; float pr;
    if      (s < 5)   { start = 1;   side = 2;  pr = 0.2f; }
    else if (s < 21)  { start = 5;   side = 4;  pr = 0.4f; }
    else if (s < 85)  { start = 21;  side = 8;  pr = 0.6f; }
    else if (s < 341) { start = 85;  side = 16; pr = 0.8f; }
    else              { start = 341; side = 32; pr = 1.0f; }
    int idx = s - start;
    int r = idx / side, c = idx % side;
    p[0] = (2.f*r + 1.f) / (float)side - 1.f;
    p[1] = (2.f*c + 1.f) / (float)side - 1.f;
    p[2] = pr;
}

// ---------------- 1. weight conversion fp32 -> fp16 ----------------
__global__ void convert_w_kernel(const float* __restrict__ qkv_w,
                                 const float* __restrict__ out_w) {
    const int n1v = (DIM*3072)/4;         // 786432 float4s
    const int n2v = (DIM*DIM)/4;          // 262144
    int idx = blockIdx.x * blockDim.x + threadIdx.x;
    if (idx < n1v) {
        float4 v = ((const float4*)qkv_w)[idx];
        __half2* dst = (__half2*)g_wqkv;
        dst[idx*2+0] = __floats2half2_rn(v.x, v.y);
        dst[idx*2+1] = __floats2half2_rn(v.z, v.w);
    } else if (idx < n1v + n2v) {
        int j = idx - n1v;
        float4 v = ((const float4*)out_w)[j];
        __half2* dst = (__half2*)g_wout;
        dst[j*2+0] = __floats2half2_rn(v.x, v.y);
        dst[j*2+1] = __floats2half2_rn(v.z, v.w);
    }
}

// ---------------- 2. adaln: wb = cond @ adaln_w + adaln_b ----------------
__global__ void adaln_kernel(const float* __restrict__ cond,
                             const float* __restrict__ adaln_w,
                             const float* __restrict__ adaln_b) {
    int b = blockIdx.y;
    int col = blockIdx.x * 128 + threadIdx.x;
    __shared__ float cs[256];
    cs[threadIdx.x]       = cond[b*256 + threadIdx.x];
    cs[threadIdx.x + 128] = cond[b*256 + threadIdx.x + 128];
    __syncthreads();
    float acc = adaln_b[col];
#pragma unroll 8
    for (int k = 0; k < 256; k++)
        acc += cs[k] * adaln_w[(size_t)k*2048 + col];
    g_wb[b*2048 + col] = acc;
}

// ---------------- 3. LayerNorm + modulation ----------------
__global__ void ln_mod_kernel(const float* __restrict__ x) {
    int row = blockIdx.x;                 // b*S + s
    int b = row / SS;
    int tid = threadIdx.x;
    const float4 v = ((const float4*)(x + (size_t)row*DIM))[tid];

    float s1 = v.x + v.y + v.z + v.w;
    float s2 = v.x*v.x + v.y*v.y + v.z*v.z + v.w*v.w;
    __shared__ float red[18];
    for (int o = 16; o; o >>= 1) {
        s1 += __shfl_down_sync(0xffffffffu, s1, o);
        s2 += __shfl_down_sync(0xffffffffu, s2, o);
    }
    if ((tid & 31) == 0) { red[tid>>5] = s1; red[8 + (tid>>5)] = s2; }
    __syncthreads();
    if (tid == 0) {
        float a = 0.f, c = 0.f;
        for (int i = 0; i < 8; i++) { a += red[i]; c += red[8+i]; }
        red[16] = a; red[17] = c;
    }
    __syncthreads();
    float mu  = red[16] * (1.f/DIM);
    float var = red[17] * (1.f/DIM) - mu*mu;
    float rstd = rsqrtf(var + 1e-5f);

    float4 w  = ((const float4*)(g_wb + b*2048))[tid];
    float4 bv = ((const float4*)(g_wb + b*2048 + 1024))[tid];
    float o0 = (v.x - mu)*rstd*(w.x + 1.f) + bv.x;
    float o1 = (v.y - mu)*rstd*(w.y + 1.f) + bv.y;
    float o2 = (v.z - mu)*rstd*(w.z + 1.f) + bv.z;
    float o3 = (v.w - mu)*rstd*(w.w + 1.f) + bv.w;
    __half2* dst = (__half2*)(g_xn + (size_t)row*DIM + tid*4);
    dst[0] = __floats2half2_rn(o0, o1);
    dst[1] = __floats2half2_rn(o2, o3);
}

// ---------------- 4. qkv GEMM (M=10920, N=3072, K=1024), fp16 wmma ----------------
__global__ void qkv_gemm_kernel(const float* __restrict__ qkv_b) {
    __shared__ __half As[64*72];
    __shared__ __half Bs[64*72];
    __shared__ float  Cs[64*72];

    int tid = threadIdx.x;
    int m0 = blockIdx.y * 64;
    int n0 = blockIdx.x * 64;
    int warp = tid >> 5, wm = warp >> 1, wn = warp & 1;

    wmma::fragment<wmma::accumulator,16,16,16,float> c0, c1;
    wmma::fill_fragment(c0, 0.f);
    wmma::fill_fragment(c1, 0.f);

    for (int kb = 0; kb < DIM/64; kb++) {
        for (int t = tid; t < 64*8; t += 256) {
            int r = t >> 3, c8 = t & 7;
            int m = m0 + r;
            float4 val = make_float4(0,0,0,0);
            if (m < MTOT)
                val = *(const float4*)(g_xn + (size_t)m*DIM + kb*64 + c8*8);
            *(float4*)(&As[r*72 + c8*8]) = val;
        }
        for (int t = tid; t < 64*8; t += 256) {
            int r = t >> 3, c8 = t & 7;
            *(float4*)(&Bs[r*72 + c8*8]) =
                *(const float4*)(g_wqkv + (size_t)(kb*64 + r)*3072 + n0 + c8*8);
        }
        __syncthreads();
#pragma unroll
        for (int ks = 0; ks < 4; ks++) {
            wmma::fragment<wmma::matrix_a,16,16,16,__half,wmma::row_major> a;
            wmma::fragment<wmma::matrix_b,16,16,16,__half,wmma::row_major> b0, b1;
            wmma::load_matrix_sync(a,  &As[(wm*16)*72 + ks*16], 72);
            wmma::load_matrix_sync(b0, &Bs[(ks*16)*72 + wn*32], 72);
            wmma::load_matrix_sync(b1, &Bs[(ks*16)*72 + wn*32 + 16], 72);
            wmma::mma_sync(c0, a, b0, c0);
            wmma::mma_sync(c1, a, b1, c1);
        }
        __syncthreads();
    }
    wmma::store_matrix_sync(&Cs[(wm*16)*72 + wn*32],      c0, 72, wmma::mem_row_major);
    wmma::store_matrix_sync(&Cs[(wm*16)*72 + wn*32 + 16], c1, 72, wmma::mem_row_major);
    __syncthreads();
    for (int t = tid; t < 64*64; t += 256) {
        int r = t >> 6, c = t & 63;
        int m = m0 + r;
        if (m < MTOT)
            g_qkv[(size_t)m*3072 + n0 + c] = Cs[r*72 + c] + qkv_b[n0 + c];
    }
}

// ---------------- 5. RoPE + layout to (B,H,SP,64) fp16 ----------------
__global__ void rope_kernel() {
    int s = blockIdx.x;            // 0..SP-1
    int b = blockIdx.y;
    int tid = threadIdx.x;
    int h = tid >> 4;
    int d0 = (tid & 15) * 4;

    size_t obase = ((size_t)(b*NH + h)*SP + s)*HD;
    if (s >= SS) {
#pragma unroll
        for (int i = 0; i < 4; i++) {
            g_q[obase + d0 + i] = __float2half(0.f);
            g_k[obase + d0 + i] = __float2half(0.f);
            g_v[obase + d0 + i] = __float2half(0.f);
        }
        return;
    }
    size_t qbase = (size_t)(b*SS + s)*3072 + h*64;

    // v passthrough
#pragma unroll
    for (int i = 0; i < 4; i++)
        g_v[obase + d0 + i] = __float2half(g_qkv[qbase + 2048 + d0 + i]);

    if (d0 < 24) {
        float p[3]; pos_of(s, p);
#pragma unroll
        for (int i = 0; i < 4; i++) {
            int d = d0 + i;                // < 24
            int comp = d >> 3, j = d & 7;
            float f = expf(1.1447298858494002f + (float)(j*16 + h) * (2.302585092994046f/128.f));
            float th = p[comp] * f;
            float sn, cs; sincosf(th, &sn, &cs);
            float q1 = g_qkv[qbase + d],        q2 = g_qkv[qbase + d + 24];
            float k1 = g_qkv[qbase + 1024 + d], k2 = g_qkv[qbase + 1024 + d + 24];
            g_q[obase + d]      = __float2half((q1*cs - q2*sn) * 0.125f);
            g_q[obase + d + 24] = __float2half((q2*cs + q1*sn) * 0.125f);
            g_k[obase + d]      = __float2half(k1*cs - k2*sn);
            g_k[obase + d + 24] = __float2half(k2*cs + k1*sn);
        }
    } else if (d0 >= 48) {
#pragma unroll
        for (int i = 0; i < 4; i++) {
            int d = d0 + i;
            g_q[obase + d] = __float2half(g_qkv[qbase + d] * 0.125f);
            g_k[obase + d] = __float2half(g_qkv[qbase + 1024 + d]);
        }
    }
}

// ---------------- 6. attention (flash-style, block-causal prefix mask) ----------------
__global__ void attn_kernel() {
    extern __shared__ char smem[];
    __half* Qs  = (__half*)smem;                 // 64x72
    __half* Ks  = Qs + 64*72;
    __half* Vs  = Ks + 64*72;
    float*  Ssm = (float*)(Vs + 64*72);          // 64x72 f32
    __half* Ps  = (__half*)(Ssm + 64*72);        // 64x72
    float*  Osm = (float*)(Ps + 64*72);          // 64x72 f32

    int tid = threadIdx.x;
    int qt = blockIdx.x, h = blockIdx.y, b = blockIdx.z;
    int q0 = qt * 64;
    int warp = tid >> 5, wm = warp >> 1, wn = warp & 1;

    size_t bh = (size_t)(b*NH + h);
    // load Q (padded arrays -> no bounds checks)
    for (int t = tid; t < 64*8; t += 256) {
        int r = t >> 3, c8 = t & 7;
        *(float4*)(&Qs[r*72 + c8*8]) =
            *(const float4*)(g_q + (bh*SP + q0 + r)*HD + c8*8);
    }
    for (int t = tid; t < 64*72; t += 256) Osm[t] = 0.f;

    float m_r = -INFINITY, l_r = 0.f;
    int kend_max = kend_of(min(q0 + 63, SS - 1));
    int nkt = (kend_max + 63) >> 6;
    __syncthreads();

    for (int kt = 0; kt < nkt; kt++) {
        int k0 = kt * 64;
        // load K,V
        for (int t = tid; t < 64*8; t += 256) {
            int r = t >> 3, c8 = t & 7;
            *(float4*)(&Ks[r*72 + c8*8]) =
                *(const float4*)(g_k + (bh*SP + k0 + r)*HD + c8*8);
            *(float4*)(&Vs[r*72 + c8*8]) =
                *(const float4*)(g_v + (bh*SP + k0 + r)*HD + c8*8);
        }
        __syncthreads();

        // S = Q @ K^T
        {
            wmma::fragment<wmma::accumulator,16,16,16,float> s0, s1;
            wmma::fill_fragment(s0, 0.f);
            wmma::fill_fragment(s1, 0.f);
#pragma unroll
            for (int ks = 0; ks < 4; ks++) {
                wmma::fragment<wmma::matrix_a,16,16,16,__half,wmma::row_major> a;
                wmma::fragment<wmma::matrix_b,16,16,16,__half,wmma::col_major> b0, b1;
                wmma::load_matrix_sync(a,  &Qs[(wm*16)*72 + ks*16], 72);
                wmma::load_matrix_sync(b0, &Ks[(wn*32)*72      + ks*16], 72);
                wmma::load_matrix_sync(b1, &Ks[(wn*32 + 16)*72 + ks*16], 72);
                wmma::mma_sync(s0, a, b0, s0);
                wmma::mma_sync(s1, a, b1, s1);
            }
            wmma::store_matrix_sync(&Ssm[(wm*16)*72 + wn*32],      s0, 72, wmma::mem_row_major);
            wmma::store_matrix_sync(&Ssm[(wm*16)*72 + wn*32 + 16], s1, 72, wmma::mem_row_major);
        }
        __syncthreads();

        // online softmax, one thread per query row
        if (tid < 64) {
            int r = tid;
            int kend = kend_of(min(q0 + r, SS - 1));
            int v = kend - k0; v = max(0, min(64, v));
            if (v > 0) {
                float mmax = -INFINITY;
                for (int j = 0; j < v; j++) mmax = fmaxf(mmax, Ssm[r*72 + j]);
                float mold = m_r;
                float mnew = fmaxf(mold, mmax);
                float alpha = __expf(mold - mnew);   // mold=-inf -> 0
                float sum = 0.f;
                for (int j = 0; j < 64; j++) {
                    float pv = (j < v) ? __expf(Ssm[r*72 + j] - mnew) : 0.f;
                    Ps[r*72 + j] = __float2half(pv);
                    sum += pv;
                }
                if (alpha != 1.f)
                    for (int d = 0; d < 64; d++) Osm[r*72 + d] *= alpha;
                l_r = l_r * alpha + sum;
                m_r = mnew;
            } else {
                for (int j = 0; j < 64; j++) Ps[r*72 + j] = __float2half(0.f);
            }
        }
        __syncthreads();

        // O += P @ V
        {
            wmma::fragment<wmma::accumulator,16,16,16,float> o0, o1;
            wmma::load_matrix_sync(o0, &Osm[(wm*16)*72 + wn*32],      72, wmma::mem_row_major);
            wmma::load_matrix_sync(o1, &Osm[(wm*16)*72 + wn*32 + 16], 72, wmma::mem_row_major);
#pragma unroll
            for (int ks = 0; ks < 4; ks++) {
                wmma::fragment<wmma::matrix_a,16,16,16,__half,wmma::row_major> a;
                wmma::fragment<wmma::matrix_b,16,16,16,__half,wmma::row_major> b0, b1;
                wmma::load_matrix_sync(a,  &Ps[(wm*16)*72 + ks*16], 72);
                wmma::load_matrix_sync(b0, &Vs[(ks*16)*72 + wn*32], 72);
                wmma::load_matrix_sync(b1, &Vs[(ks*16)*72 + wn*32 + 16], 72);
                wmma::mma_sync(o0, a, b0, o0);
                wmma::mma_sync(o1, a, b1, o1);
            }
            wmma::store_matrix_sync(&Osm[(wm*16)*72 + wn*32],      o0, 72, wmma::mem_row_major);
            wmma::store_matrix_sync(&Osm[(wm*16)*72 + wn*32 + 16], o1, 72, wmma::mem_row_major);
        }
        __syncthreads();
    }

    if (tid < 64) {
        int s = q0 + tid;
        if (s < SS) {
            float inv = 1.f / l_r;
            __half* dst = g_o + (size_t)(b*SS + s)*DIM + h*64;
            for (int d = 0; d < 64; d++)
                dst[d] = __float2half(Osm[tid*72 + d] * inv);
        }
    }
}

// ---------------- 7. out projection + bias + skip ----------------
__global__ void proj_gemm_kernel(const float* __restrict__ out_b,
                                 const float* __restrict__ x,
                                 float* __restrict__ out) {
    __shared__ __half As[64*72];
    __shared__ __half Bs[64*72];
    __shared__ float  Cs[64*72];

    int tid = threadIdx.x;
    int m0 = blockIdx.y * 64;
    int n0 = blockIdx.x * 64;
    int warp = tid >> 5, wm = warp >> 1, wn = warp & 1;

    wmma::fragment<wmma::accumulator,16,16,16,float> c0, c1;
    wmma::fill_fragment(c0, 0.f);
    wmma::fill_fragment(c1, 0.f);

    for (int kb = 0; kb < DIM/64; kb++) {
        for (int t = tid; t < 64*8; t += 256) {
            int r = t >> 3, c8 = t & 7;
            int m = m0 + r;
            float4 val = make_float4(0,0,0,0);
            if (m < MTOT)
                val = *(const float4*)(g_o + (size_t)m*DIM + kb*64 + c8*8);
            *(float4*)(&As[r*72 + c8*8]) = val;
        }
        for (int t = tid; t < 64*8; t += 256) {
            int r = t >> 3, c8 = t & 7;
            *(float4*)(&Bs[r*72 + c8*8]) =
                *(const float4*)(g_wout + (size_t)(kb*64 + r)*DIM + n0 + c8*8);
        }
        __syncthreads();
#pragma unroll
        for (int ks = 0; ks < 4; ks++) {
            wmma::fragment<wmma::matrix_a,16,16,16,__half,wmma::row_major> a;
            wmma::fragment<wmma::matrix_b,16,16,16,__half,wmma::row_major> b0, b1;
            wmma::load_matrix_sync(a,  &As[(wm*16)*72 + ks*16], 72);
            wmma::load_matrix_sync(b0, &Bs[(ks*16)*72 + wn*32], 72);
            wmma::load_matrix_sync(b1, &Bs[(ks*16)*72 + wn*32 + 16], 72);
            wmma::mma_sync(c0, a, b0, c0);
            wmma::mma_sync(c1, a, b1, c1);
        }
        __syncthreads();
    }
    wmma::store_matrix_sync(&Cs[(wm*16)*72 + wn*32],      c0, 72, wmma::mem_row_major);
    wmma::store_matrix_sync(&Cs[(wm*16)*72 + wn*32 + 16], c1, 72, wmma::mem_row_major);
    __syncthreads();
    for (int t = tid; t < 64*64; t += 256) {
        int r = t >> 6, c = t & 63;
        int m = m0 + r;
        if (m < MTOT) {
            int col = n0 + c;
            out[(size_t)m*DIM + col] = Cs[r*72 + c] + out_b[col] + x[(size_t)m*DIM + col];
        }
    }
}

// ---------------- launch ----------------
extern "C" void kernel_launch(void* const* d_in, const int* in_sizes, int n_in,
                              void* d_out, int out_size) {
    const float* x       = (const float*)d_in[0];
    const float* cond    = (const float*)d_in[1];
    const float* adaln_w = (const float*)d_in[2];
    const float* adaln_b = (const float*)d_in[3];
    const float* qkv_w   = (const float*)d_in[4];
    const float* qkv_b   = (const float*)d_in[5];
    const float* out_w   = (const float*)d_in[6];
    const float* out_b   = (const float*)d_in[7];
    float* out = (float*)d_out;

    cudaFuncSetAttribute(attn_kernel, cudaFuncAttributeMaxDynamicSharedMemorySize, 73728);

    convert_w_kernel<<<4096, 256>>>(qkv_w, out_w);
    adaln_kernel<<<dim3(16, BB), 128>>>(cond, adaln_w, adaln_b);
    ln_mod_kernel<<<MTOT, 256>>>(x);
    qkv_gemm_kernel<<<dim3(48, 171), 256>>>(qkv_b);
    rope_kernel<<<dim3(SP, BB), 256>>>();
    attn_kernel<<<dim3(22, NH, BB), 256, 73728>>>();
    proj_gemm_kernel<<<dim3(16, 171), 256>>>(out_b, x, out);
}

// round 5
// speedup vs baseline: 1.1475x; 1.1475x over previous
#include <cuda_runtime.h>
#include <cuda_fp16.h>
#include <mma.h>
#include <cstdint>

using namespace nvcuda;

#define BB 8
#define SS 1365
#define SP 1408
#define DIM 1024
#define NH 16
#define HD 64
#define MTOT (BB*SS)   // 10920

// ---------------- scratch (device globals; never passed from host!) ----------------
__device__ __half g_xn[(size_t)BB*SS*DIM];
__device__ float  g_wb[BB*2048];
__device__ float  g_qkv[(size_t)BB*SS*3072];
__device__ __half g_q[(size_t)BB*NH*SP*HD];
__device__ __half g_k[(size_t)BB*NH*SP*HD];
__device__ __half g_v[(size_t)BB*NH*SP*HD];
__device__ __half g_o[(size_t)BB*SS*DIM];
__device__ __half g_wqkv[(size_t)DIM*3072];
__device__ __half g_wout[(size_t)DIM*DIM];

// ---------------- helpers ----------------
__device__ __forceinline__ int kend_of(int s) {
    if (s < 1)   return 1;
    if (s < 5)   return 5;
    if (s < 21)  return 21;
    if (s < 85)  return 85;
    if (s < 341) return 341;
    return 1365;
}

__device__ __forceinline__ void pos_of(int s, float* p) {
    if (s == 0) { p[0] = 0.f; p[1] = 0.f; p[2] = 0.f; return; }
    int start, side; float pr;
    if      (s < 5)   { start = 1;   side = 2;  pr = 0.2f; }
    else if (s < 21)  { start = 5;   side = 4;  pr = 0.4f; }
    else if (s < 85)  { start = 21;  side = 8;  pr = 0.6f; }
    else if (s < 341) { start = 85;  side = 16; pr = 0.8f; }
    else              { start = 341; side = 32; pr = 1.0f; }
    int idx = s - start;
    int r = idx / side, c = idx % side;
    p[0] = (2.f*r + 1.f) / (float)side - 1.f;
    p[1] = (2.f*c + 1.f) / (float)side - 1.f;
    p[2] = pr;
}

// ---------------- 1. weight conversion ----------------
__global__ void convert_w_kernel(const float* __restrict__ qkv_w,
                                 const float* __restrict__ out_w) {
    const int n1v = (DIM*3072)/4;
    const int n2v = (DIM*DIM)/4;
    int idx = blockIdx.x * blockDim.x + threadIdx.x;
    if (idx < n1v) {
        float4 v = ((const float4*)qkv_w)[idx];
        __half2* dst = (__half2*)g_wqkv;
        dst[idx*2+0] = __floats2half2_rn(v.x, v.y);
        dst[idx*2+1] = __floats2half2_rn(v.z, v.w);
    } else if (idx < n1v + n2v) {
        int j = idx - n1v;
        float4 v = ((const float4*)out_w)[j];
        __half2* dst = (__half2*)g_wout;
        dst[j*2+0] = __floats2half2_rn(v.x, v.y);
        dst[j*2+1] = __floats2half2_rn(v.z, v.w);
    }
}

// ---------------- 2. adaln ----------------
__global__ void adaln_kernel(const float* __restrict__ cond,
                             const float* __restrict__ adaln_w,
                             const float* __restrict__ adaln_b) {
    int b = blockIdx.y;
    int col = blockIdx.x * 128 + threadIdx.x;
    __shared__ float cs[256];
    cs[threadIdx.x]       = cond[b*256 + threadIdx.x];
    cs[threadIdx.x + 128] = cond[b*256 + threadIdx.x + 128];
    __syncthreads();
    float acc = adaln_b[col];
#pragma unroll 8
    for (int k = 0; k < 256; k++)
        acc += cs[k] * adaln_w[(size_t)k*2048 + col];
    g_wb[b*2048 + col] = acc;
}

// ---------------- 3. LayerNorm + modulation ----------------
__global__ void ln_mod_kernel(const float* __restrict__ x) {
    int row = blockIdx.x;
    int b = row / SS;
    int tid = threadIdx.x;
    const float4 v = ((const float4*)(x + (size_t)row*DIM))[tid];

    float s1 = v.x + v.y + v.z + v.w;
    float s2 = v.x*v.x + v.y*v.y + v.z*v.z + v.w*v.w;
    __shared__ float red[18];
    for (int o = 16; o; o >>= 1) {
        s1 += __shfl_down_sync(0xffffffffu, s1, o);
        s2 += __shfl_down_sync(0xffffffffu, s2, o);
    }
    if ((tid & 31) == 0) { red[tid>>5] = s1; red[8 + (tid>>5)] = s2; }
    __syncthreads();
    if (tid == 0) {
        float a = 0.f, c = 0.f;
        for (int i = 0; i < 8; i++) { a += red[i]; c += red[8+i]; }
        red[16] = a; red[17] = c;
    }
    __syncthreads();
    float mu  = red[16] * (1.f/DIM);
    float var = red[17] * (1.f/DIM) - mu*mu;
    float rstd = rsqrtf(var + 1e-5f);

    float4 w  = ((const float4*)(g_wb + b*2048))[tid];
    float4 bv = ((const float4*)(g_wb + b*2048 + 1024))[tid];
    float o0 = (v.x - mu)*rstd*(w.x + 1.f) + bv.x;
    float o1 = (v.y - mu)*rstd*(w.y + 1.f) + bv.y;
    float o2 = (v.z - mu)*rstd*(w.z + 1.f) + bv.z;
    float o3 = (v.w - mu)*rstd*(w.w + 1.f) + bv.w;
    __half2* dst = (__half2*)(g_xn + (size_t)row*DIM + tid*4);
    dst[0] = __floats2half2_rn(o0, o1);
    dst[1] = __floats2half2_rn(o2, o3);
}

// ---------------- 4/7. unified GEMM; MODE 0: qkv (g_xn@g_wqkv->g_qkv), MODE 1: proj (g_o@g_wout+skip->out)
template<int MODE>
__global__ void gemm128_kernel(const float* __restrict__ bias,
                               const float* __restrict__ skip,
                               float* __restrict__ outp) {
    constexpr int N = (MODE == 0) ? 3072 : 1024;
    // device-side binding of scratch globals (host must not pass their addresses)
    const __half* A  = (MODE == 0) ? g_xn   : g_o;
    const __half* Bw = (MODE == 0) ? g_wqkv : g_wout;
    float* Cout      = (MODE == 0) ? g_qkv  : outp;

    extern __shared__ char sm[];
    __half* As = (__half*)sm;                         // [2][128*72]
    __half* Bs = (__half*)(sm + 2*128*72*2);          // [2][64*72]
    float*  Cs = (float*)sm;                          // epilogue reuse

    int tid = threadIdx.x;
    int m0 = blockIdx.y * 128;
    int n0 = blockIdx.x * 64;
    int warp = tid >> 5, wm = warp >> 1, wn = warp & 1;

    wmma::fragment<wmma::accumulator,16,16,16,float> acc[2][2];
#pragma unroll
    for (int i = 0; i < 2; i++)
#pragma unroll
        for (int j = 0; j < 2; j++)
            wmma::fill_fragment(acc[i][j], 0.f);

    {
        for (int t = tid; t < 128*8; t += 256) {
            int r = t >> 3, c8 = t & 7;
            int m = m0 + r;
            float4 val = make_float4(0,0,0,0);
            if (m < MTOT) val = *(const float4*)(A + (size_t)m*DIM + c8*8);
            *(float4*)(&As[r*72 + c8*8]) = val;
        }
        for (int t = tid; t < 64*8; t += 256) {
            int r = t >> 3, c8 = t & 7;
            *(float4*)(&Bs[r*72 + c8*8]) =
                *(const float4*)(Bw + (size_t)r*N + n0 + c8*8);
        }
    }
    __syncthreads();

    for (int kb = 0; kb < DIM/64; kb++) {
        int buf = kb & 1;
        if (kb + 1 < DIM/64) {
            int nb = buf ^ 1;
            for (int t = tid; t < 128*8; t += 256) {
                int r = t >> 3, c8 = t & 7;
                int m = m0 + r;
                float4 val = make_float4(0,0,0,0);
                if (m < MTOT)
                    val = *(const float4*)(A + (size_t)m*DIM + (kb+1)*64 + c8*8);
                *(float4*)(&As[nb*128*72 + r*72 + c8*8]) = val;
            }
            for (int t = tid; t < 64*8; t += 256) {
                int r = t >> 3, c8 = t & 7;
                *(float4*)(&Bs[nb*64*72 + r*72 + c8*8]) =
                    *(const float4*)(Bw + (size_t)((kb+1)*64 + r)*N + n0 + c8*8);
            }
        }
#pragma unroll
        for (int ks = 0; ks < 4; ks++) {
            wmma::fragment<wmma::matrix_a,16,16,16,__half,wmma::row_major> a0, a1;
            wmma::fragment<wmma::matrix_b,16,16,16,__half,wmma::row_major> b0, b1;
            wmma::load_matrix_sync(a0, &As[buf*128*72 + (wm*32)*72      + ks*16], 72);
            wmma::load_matrix_sync(a1, &As[buf*128*72 + (wm*32 + 16)*72 + ks*16], 72);
            wmma::load_matrix_sync(b0, &Bs[buf*64*72  + (ks*16)*72 + wn*32], 72);
            wmma::load_matrix_sync(b1, &Bs[buf*64*72  + (ks*16)*72 + wn*32 + 16], 72);
            wmma::mma_sync(acc[0][0], a0, b0, acc[0][0]);
            wmma::mma_sync(acc[0][1], a0, b1, acc[0][1]);
            wmma::mma_sync(acc[1][0], a1, b0, acc[1][0]);
            wmma::mma_sync(acc[1][1], a1, b1, acc[1][1]);
        }
        __syncthreads();
    }

#pragma unroll
    for (int i = 0; i < 2; i++)
#pragma unroll
        for (int j = 0; j < 2; j++)
            wmma::store_matrix_sync(&Cs[(wm*32 + i*16)*72 + wn*32 + j*16],
                                    acc[i][j], 72, wmma::mem_row_major);
    __syncthreads();
    for (int t = tid; t < 128*64; t += 256) {
        int r = t >> 6, c = t & 63;
        int m = m0 + r;
        if (m < MTOT) {
            int col = n0 + c;
            float v = Cs[r*72 + c] + bias[col];
            if (MODE == 1) v += skip[(size_t)m*N + col];
            Cout[(size_t)m*N + col] = v;
        }
    }
}

// ---------------- 5. RoPE ----------------
__global__ void rope_kernel() {
    int s = blockIdx.x;
    int b = blockIdx.y;
    int tid = threadIdx.x;
    int h = tid >> 4;
    int d0 = (tid & 15) * 4;

    size_t obase = ((size_t)(b*NH + h)*SP + s)*HD;
    if (s >= SS) {
#pragma unroll
        for (int i = 0; i < 4; i++) {
            g_q[obase + d0 + i] = __float2half(0.f);
            g_k[obase + d0 + i] = __float2half(0.f);
            g_v[obase + d0 + i] = __float2half(0.f);
        }
        return;
    }
    size_t qbase = (size_t)(b*SS + s)*3072 + h*64;

#pragma unroll
    for (int i = 0; i < 4; i++)
        g_v[obase + d0 + i] = __float2half(g_qkv[qbase + 2048 + d0 + i]);

    if (d0 < 24) {
        float p[3]; pos_of(s, p);
#pragma unroll
        for (int i = 0; i < 4; i++) {
            int d = d0 + i;
            int comp = d >> 3, j = d & 7;
            float f = expf(1.1447298858494002f + (float)(j*16 + h) * (2.302585092994046f/128.f));
            float th = p[comp] * f;
            float sn, cs; sincosf(th, &sn, &cs);
            float q1 = g_qkv[qbase + d],        q2 = g_qkv[qbase + d + 24];
            float k1 = g_qkv[qbase + 1024 + d], k2 = g_qkv[qbase + 1024 + d + 24];
            g_q[obase + d]      = __float2half((q1*cs - q2*sn) * 0.125f);
            g_q[obase + d + 24] = __float2half((q2*cs + q1*sn) * 0.125f);
            g_k[obase + d]      = __float2half(k1*cs - k2*sn);
            g_k[obase + d + 24] = __float2half(k2*cs + k1*sn);
        }
    } else if (d0 >= 48) {
#pragma unroll
        for (int i = 0; i < 4; i++) {
            int d = d0 + i;
            g_q[obase + d] = __float2half(g_qkv[qbase + d] * 0.125f);
            g_k[obase + d] = __float2half(g_qkv[qbase + 1024 + d]);
        }
    }
}

// ---------------- 6. attention (flash-style, branch-free parallel softmax) ----------------
__global__ void attn_kernel() {
    extern __shared__ char smem[];
    __half* Qs  = (__half*)smem;                 // 64x72
    __half* Ks  = Qs + 64*72;
    __half* Vs  = Ks + 64*72;
    float*  Ssm = (float*)(Vs + 64*72);          // 64x72 f32
    __half* Ps  = (__half*)(Ssm + 64*72);        // 64x72
    float*  Osm = (float*)(Ps + 64*72);          // 64x72 f32
    float*  al_s = (float*)(Osm + 64*72);        // 64

    int tid = threadIdx.x;
    int qt = blockIdx.x, h = blockIdx.y, b = blockIdx.z;
    int q0 = qt * 64;
    int warp = tid >> 5, wm = warp >> 1, wn = warp & 1;

    size_t bh = (size_t)(b*NH + h);
    for (int t = tid; t < 64*8; t += 256) {
        int r = t >> 3, c8 = t & 7;
        *(float4*)(&Qs[r*72 + c8*8]) =
            *(const float4*)(g_q + (bh*SP + q0 + r)*HD + c8*8);
    }
    for (int t = tid; t < 64*72; t += 256) Osm[t] = 0.f;

    // quad per row: 4 threads/row, 16 cols each; m/l replicated in registers across the quad
    int srow = tid >> 2;
    int scol0 = (tid & 3) * 16;
    int kend_r = kend_of(min(q0 + srow, SS - 1));
    float m_r = -INFINITY, l_r = 0.f;

    int kend_max = kend_of(min(q0 + 63, SS - 1));
    int nkt = (kend_max + 63) >> 6;
    __syncthreads();

    for (int kt = 0; kt < nkt; kt++) {
        int k0 = kt * 64;
        for (int t = tid; t < 64*8; t += 256) {
            int r = t >> 3, c8 = t & 7;
            *(float4*)(&Ks[r*72 + c8*8]) =
                *(const float4*)(g_k + (bh*SP + k0 + r)*HD + c8*8);
            *(float4*)(&Vs[r*72 + c8*8]) =
                *(const float4*)(g_v + (bh*SP + k0 + r)*HD + c8*8);
        }
        __syncthreads();

        // S = Q @ K^T
        {
            wmma::fragment<wmma::accumulator,16,16,16,float> s0, s1;
            wmma::fill_fragment(s0, 0.f);
            wmma::fill_fragment(s1, 0.f);
#pragma unroll
            for (int ks = 0; ks < 4; ks++) {
                wmma::fragment<wmma::matrix_a,16,16,16,__half,wmma::row_major> a;
                wmma::fragment<wmma::matrix_b,16,16,16,__half,wmma::col_major> b0, b1;
                wmma::load_matrix_sync(a,  &Qs[(wm*16)*72 + ks*16], 72);
                wmma::load_matrix_sync(b0, &Ks[(wn*32)*72      + ks*16], 72);
                wmma::load_matrix_sync(b1, &Ks[(wn*32 + 16)*72 + ks*16], 72);
                wmma::mma_sync(s0, a, b0, s0);
                wmma::mma_sync(s1, a, b1, s1);
            }
            wmma::store_matrix_sync(&Ssm[(wm*16)*72 + wn*32],      s0, 72, wmma::mem_row_major);
            wmma::store_matrix_sync(&Ssm[(wm*16)*72 + wn*32 + 16], s1, 72, wmma::mem_row_major);
        }
        __syncthreads();

        // branch-free online softmax (all lanes execute all shuffles; no divergence)
        {
            int v = kend_r - k0; v = max(0, min(64, v));
            float pv[16];
            float mloc = -INFINITY;
#pragma unroll
            for (int j = 0; j < 16; j++) {
                int c = scol0 + j;
                pv[j] = (c < v) ? Ssm[srow*72 + c] : -INFINITY;
                mloc = fmaxf(mloc, pv[j]);
            }
            mloc = fmaxf(mloc, __shfl_xor_sync(0xffffffffu, mloc, 1));
            mloc = fmaxf(mloc, __shfl_xor_sync(0xffffffffu, mloc, 2));
            // v==0 only possible at kt>0 where m_r finite -> mnew=m_r, alpha=1, sum=0
            float mnew = fmaxf(m_r, mloc);
            float sum = 0.f;
#pragma unroll
            for (int j = 0; j < 16; j++) {
                float e = (scol0 + j < v) ? __expf(pv[j] - mnew) : 0.f;
                Ps[srow*72 + scol0 + j] = __float2half(e);
                sum += e;
            }
            sum += __shfl_xor_sync(0xffffffffu, sum, 1);
            sum += __shfl_xor_sync(0xffffffffu, sum, 2);
            float alpha = __expf(m_r - mnew);   // kt=0: exp(-inf)=0; replicated in quad
            l_r = l_r * alpha + sum;
            m_r = mnew;
            if ((tid & 3) == 0) al_s[srow] = alpha;
        }
        __syncthreads();

        if (kt > 0) {
            for (int t = tid; t < 64*64; t += 256) {
                int r = t >> 6, c = t & 63;
                Osm[r*72 + c] *= al_s[r];
            }
            __syncthreads();
        }

        // O += P @ V
        {
            wmma::fragment<wmma::accumulator,16,16,16,float> o0, o1;
            wmma::load_matrix_sync(o0, &Osm[(wm*16)*72 + wn*32],      72, wmma::mem_row_major);
            wmma::load_matrix_sync(o1, &Osm[(wm*16)*72 + wn*32 + 16], 72, wmma::mem_row_major);
#pragma unroll
            for (int ks = 0; ks < 4; ks++) {
                wmma::fragment<wmma::matrix_a,16,16,16,__half,wmma::row_major> a;
                wmma::fragment<wmma::matrix_b,16,16,16,__half,wmma::row_major> b0, b1;
                wmma::load_matrix_sync(a,  &Ps[(wm*16)*72 + ks*16], 72);
                wmma::load_matrix_sync(b0, &Vs[(ks*16)*72 + wn*32], 72);
                wmma::load_matrix_sync(b1, &Vs[(ks*16)*72 + wn*32 + 16], 72);
                wmma::mma_sync(o0, a, b0, o0);
                wmma::mma_sync(o1, a, b1, o1);
            }
            wmma::store_matrix_sync(&Osm[(wm*16)*72 + wn*32],      o0, 72, wmma::mem_row_major);
            wmma::store_matrix_sync(&Osm[(wm*16)*72 + wn*32 + 16], o1, 72, wmma::mem_row_major);
        }
        __syncthreads();
    }

    {
        int s = q0 + srow;
        if (s < SS) {
            float inv = 1.f / l_r;
            __half* dst = g_o + (size_t)(b*SS + s)*DIM + h*64 + scol0;
#pragma unroll
            for (int d = 0; d < 16; d++)
                dst[d] = __float2half(Osm[srow*72 + scol0 + d] * inv);
        }
    }
}

// ---------------- launch ----------------
extern "C" void kernel_launch(void* const* d_in, const int* in_sizes, int n_in,
                              void* d_out, int out_size) {
    const float* x       = (const float*)d_in[0];
    const float* cond    = (const float*)d_in[1];
    const float* adaln_w = (const float*)d_in[2];
    const float* adaln_b = (const float*)d_in[3];
    const float* qkv_w   = (const float*)d_in[4];
    const float* qkv_b   = (const float*)d_in[5];
    const float* out_w   = (const float*)d_in[6];
    const float* out_b   = (const float*)d_in[7];
    float* out = (float*)d_out;

    const int GEMM_SMEM = 2*128*72*2 + 2*64*72*2;   // 55296
    const int ATTN_SMEM = 64*72*2*3 + 64*72*4 + 64*72*2 + 64*72*4 + 64*4;  // 74048
    cudaFuncSetAttribute(gemm128_kernel<0>, cudaFuncAttributeMaxDynamicSharedMemorySize, GEMM_SMEM);
    cudaFuncSetAttribute(gemm128_kernel<1>, cudaFuncAttributeMaxDynamicSharedMemorySize, GEMM_SMEM);
    cudaFuncSetAttribute(attn_kernel, cudaFuncAttributeMaxDynamicSharedMemorySize, ATTN_SMEM);

    convert_w_kernel<<<4096, 256>>>(qkv_w, out_w);
    adaln_kernel<<<dim3(16, BB), 128>>>(cond, adaln_w, adaln_b);
    ln_mod_kernel<<<MTOT, 256>>>(x);
    gemm128_kernel<0><<<dim3(48, 86), 256, GEMM_SMEM>>>(qkv_b, nullptr, nullptr);
    rope_kernel<<<dim3(SP, BB), 256>>>();
    attn_kernel<<<dim3(22, NH, BB), 256, ATTN_SMEM>>>();
    gemm128_kernel<1><<<dim3(16, 86), 256, GEMM_SMEM>>>(out_b, x, out);
}